// round 9
// baseline (speedup 1.0000x reference)
#include <cuda_runtime.h>
#include <cuda_fp16.h>
#include <cstdint>
#include <math.h>

#define BB   64
#define AA   128
#define INC  128
#define OUTC 64
#define NTOK 8192
#define LOG2E 1.4426950408889634f

// ---- scratch (device globals; no allocations allowed) ----------------------
__device__ float g_Vn[NTOK * OUTC];
__device__ float g_On[NTOK * OUTC];
__device__ float g_Op[2 * NTOK * OUTC];      // attention partial O per key-half
__device__ float g_part[OUTC * OUTC * AA];   // sim split-K partials [ij][a]
__device__ __align__(256) __half g_Qh[NTOK * OUTC];
__device__ __align__(256) __half g_Kh[NTOK * OUTC];
__device__ __align__(256) __half g_Vh[NTOK * OUTC];

// ---- helpers ----------------------------------------------------------------
__device__ __forceinline__ uint32_t sptr(const void* p) {
    return (uint32_t)__cvta_generic_to_shared(p);
}
__device__ __forceinline__ void cp16(void* smp, const void* gp) {
    asm volatile("cp.async.cg.shared.global [%0], [%1], 16;" :: "r"(sptr(smp)), "l"(gp));
}
#define CP_COMMIT()  asm volatile("cp.async.commit_group;")
#define CP_WAIT(n)   asm volatile("cp.async.wait_group %0;" :: "n"(n))
#define BARG(id)     asm volatile("bar.sync %0, 128;" :: "r"(id) : "memory")

// pack two fp32 into f16x2 and take exp2 elementwise
__device__ __forceinline__ uint32_t ex2_pack(float x, float y) {
    uint32_t d;
    asm("{\n\t"
        ".reg .b32 t;\n\t"
        "cvt.rn.f16x2.f32 t, %2, %1;\n\t"
        "ex2.approx.f16x2 %0, t;\n\t"
        "}" : "=r"(d) : "f"(x), "f"(y));
    return d;
}

#define LDSM4(d0,d1,d2,d3,a) \
  asm volatile("ldmatrix.sync.aligned.m8n8.x4.shared.b16 {%0,%1,%2,%3},[%4];" \
    : "=r"(d0),"=r"(d1),"=r"(d2),"=r"(d3) : "r"(a))
#define LDSM4T(d0,d1,d2,d3,a) \
  asm volatile("ldmatrix.sync.aligned.m8n8.x4.trans.shared.b16 {%0,%1,%2,%3},[%4];" \
    : "=r"(d0),"=r"(d1),"=r"(d2),"=r"(d3) : "r"(a))
#define MMA(d,a,b0,b1) \
  asm volatile("mma.sync.aligned.m16n8k16.row.col.f32.f16.f16.f32 " \
    "{%0,%1,%2,%3},{%4,%5,%6,%7},{%8,%9},{%0,%1,%2,%3};" \
    : "+f"(d[0]),"+f"(d[1]),"+f"(d[2]),"+f"(d[3]) \
    : "r"(a[0]),"r"(a[1]),"r"(a[2]),"r"(a[3]),"r"(b0),"r"(b1))

__device__ __forceinline__ uint32_t packh(float x, float y) {
    __half2 hh = __floats2half2_rn(x, y);
    return *reinterpret_cast<uint32_t*>(&hh);
}

// ---------------------------------------------------------------------------
// Kernel A: projections. grid (64 batches, 3 matrices, 2 a-halves), 256 thr.
// ---------------------------------------------------------------------------
__global__ void proj_kernel(const float* __restrict__ feat,
                            const float* __restrict__ Wq, const float* __restrict__ bq,
                            const float* __restrict__ Wk, const float* __restrict__ bk,
                            const float* __restrict__ Wv, const float* __restrict__ bv)
{
    extern __shared__ float sA[];
    float* fs = sA;             // 64 x 132
    float* ws = sA + 64 * 132;  // 64 x 132

    const int b   = blockIdx.x;
    const int m   = blockIdx.y;
    const int a0  = blockIdx.z * 64;
    const int tid = threadIdx.x;
    const float* fb = feat + (size_t)b * INC * AA;

    const float* W    = (m == 0) ? Wq : (m == 1) ? Wk : Wv;
    const float* bias = (m == 0) ? bq : (m == 1) ? bk : bv;
    const float  scale = (m == 0) ? 0.125f * LOG2E : 1.0f;
    __half* Hh = (m == 0) ? g_Qh : (m == 1) ? g_Kh : g_Vh;

    #pragma unroll
    for (int i = 0; i < 32; i++) {
        int idx = tid + i * 256;
        int c = idx >> 6, a = idx & 63;
        fs[a * 132 + c] = fb[c * 128 + a0 + a];
    }
    #pragma unroll
    for (int i = 0; i < 32; i++) {
        int idx = tid + i * 256;
        int j = idx >> 7, c = idx & 127;
        ws[j * 132 + c] = W[idx];
    }
    __syncthreads();

    const int ty = tid >> 4;
    const int tx = tid & 15;

    float acc[4][4] = {};
    for (int c = 0; c < 128; c += 4) {
        float4 fv[4], wv[4];
        #pragma unroll
        for (int ii = 0; ii < 4; ii++)
            fv[ii] = *(const float4*)(fs + (ty * 4 + ii) * 132 + c);
        #pragma unroll
        for (int jj = 0; jj < 4; jj++)
            wv[jj] = *(const float4*)(ws + (tx * 4 + jj) * 132 + c);
        #pragma unroll
        for (int ii = 0; ii < 4; ii++)
            #pragma unroll
            for (int jj = 0; jj < 4; jj++) {
                acc[ii][jj] += fv[ii].x * wv[jj].x;
                acc[ii][jj] += fv[ii].y * wv[jj].y;
                acc[ii][jj] += fv[ii].z * wv[jj].z;
                acc[ii][jj] += fv[ii].w * wv[jj].w;
            }
    }

    float4 bv4 = *(const float4*)(bias + tx * 4);
    #pragma unroll
    for (int ii = 0; ii < 4; ii++) {
        size_t n = (size_t)b * AA + a0 + ty * 4 + ii;
        float o0 = (acc[ii][0] + bv4.x) * scale;
        float o1 = (acc[ii][1] + bv4.y) * scale;
        float o2 = (acc[ii][2] + bv4.z) * scale;
        float o3 = (acc[ii][3] + bv4.w) * scale;
        *reinterpret_cast<uint32_t*>(Hh + n * OUTC + tx * 4)     = packh(o0, o1);
        *reinterpret_cast<uint32_t*>(Hh + n * OUTC + tx * 4 + 2) = packh(o2, o3);
        if (m == 2) {
            float ss = o0*o0 + o1*o1 + o2*o2 + o3*o3;
            ss += __shfl_xor_sync(0xffffffffu, ss, 1);
            ss += __shfl_xor_sync(0xffffffffu, ss, 2);
            ss += __shfl_xor_sync(0xffffffffu, ss, 4);
            ss += __shfl_xor_sync(0xffffffffu, ss, 8);
            float inv = 1.0f / fmaxf(sqrtf(ss), 1e-12f);
            float4 t;
            t.x = o0 * inv; t.y = o1 * inv; t.z = o2 * inv; t.w = o3 * inv;
            *(float4*)(g_Vn + n * OUTC + tx * 4) = t;
        }
    }
}

// ---------------------------------------------------------------------------
// Kernel B: attention on HMMA fp16, split-K over keys.
// grid = 256: CTA (q-tile = bx>>1, key-half = bx&1), each does 64 key tiles.
// 2 CTAs/SM (4 warps/SMSP) for latency hiding; all 148 SMs busy.
// Emits raw partial O to g_Op[half]; combine kernel sums + l2norms.
// ---------------------------------------------------------------------------
__global__ void __launch_bounds__(256, 2) attn_kernel()
{
    extern __shared__ __half sm[];
    const int tid  = threadIdx.x, lane = tid & 31, w = tid >> 5;
    const int g    = w >> 2;
    const int wl   = w & 3;
    const int gtid = tid & 127;
    const int q0   = (blockIdx.x >> 1) * 64;
    const int kh   = blockIdx.x & 1;
    const int kt0  = kh * 64;            // this CTA's key-tile range [kt0, kt0+64)

    __half* QH = sm;            // 64 x 72 = 4608
    __half* ST = sm + 4608;     // 4 stages x 9216: [Kh,Vh] x 4608

    #pragma unroll
    for (int i = 0; i < 2; i++) {
        int idx = tid + i * 256, row = idx >> 3, c8 = idx & 7;
        cp16(QH + row * 72 + c8 * 8, g_Qh + (size_t)(q0 + row) * 64 + c8 * 8);
    }
    {
        __half* S0 = ST + (2 * g) * 9216;
        #pragma unroll
        for (int i = 0; i < 4; i++) {
            int idx = gtid + i * 128, row = idx >> 3, c8 = idx & 7;
            size_t gg = (size_t)((kt0 + g) * 64 + row) * 64 + c8 * 8;
            cp16(S0        + row * 72 + c8 * 8, g_Kh + gg);
            cp16(S0 + 4608 + row * 72 + c8 * 8, g_Vh + gg);
        }
    }
    CP_COMMIT();
    CP_WAIT(0);
    __syncthreads();

    // persistent Q fragments
    uint32_t qh[4][4];
    const int r0 = wl * 16;
    {
        int row  = r0 + (lane & 15);
        int coff = (lane >> 4) * 8;
        #pragma unroll
        for (int kk = 0; kk < 4; kk++)
            LDSM4(qh[kk][0], qh[kk][1], qh[kk][2], qh[kk][3],
                  sptr(QH + row * 72 + kk * 16 + coff));
    }

    float o[8][4];
    #pragma unroll
    for (int j = 0; j < 8; j++) { o[j][0] = o[j][1] = o[j][2] = o[j][3] = 0.f; }

    const uint32_t krow = ((lane & 7) * 72 + (lane >> 3) * 8) * 2;
    const uint32_t vrow = lane * 144;
    const int bar_id = g + 1;

    for (int kt = kt0 + g; kt < kt0 + 64; kt += 2) {
        __half* CUR = ST + (2 * g + ((kt >> 1) & 1)) * 9216;
        if (kt + 2 < kt0 + 64) {
            __half* NXT = ST + (2 * g + (((kt + 2) >> 1) & 1)) * 9216;
            #pragma unroll
            for (int i = 0; i < 4; i++) {
                int idx = gtid + i * 128, row = idx >> 3, c8 = idx & 7;
                size_t gg = (size_t)((kt + 2) * 64 + row) * 64 + c8 * 8;
                cp16(NXT        + row * 72 + c8 * 8, g_Kh + gg);
                cp16(NXT + 4608 + row * 72 + c8 * 8, g_Vh + gg);
            }
            CP_COMMIT();
            CP_WAIT(1);
        } else {
            CP_WAIT(0);
        }
        BARG(bar_id);

        const uint32_t khb = sptr(CUR) + krow;

        // S = qh * Kh
        float s[8][4];
        #pragma unroll
        for (int j = 0; j < 8; j++) {
            uint32_t bh[8];
            uint32_t off = j * (8 * 72 * 2);
            LDSM4(bh[0], bh[1], bh[2], bh[3], khb + off);
            LDSM4(bh[4], bh[5], bh[6], bh[7], khb + off + 64);
            s[j][0] = s[j][1] = s[j][2] = s[j][3] = 0.f;
            #pragma unroll
            for (int kk = 0; kk < 4; kk++)
                MMA(s[j], qh[kk], bh[kk * 2], bh[kk * 2 + 1]);
        }

        // P = exp2(S) -> f16x2 A fragments
        uint32_t ph[4][4];
        #pragma unroll
        for (int kk = 0; kk < 4; kk++) {
            int j0 = kk * 2, j1 = kk * 2 + 1;
            ph[kk][0] = ex2_pack(s[j0][0], s[j0][1]);
            ph[kk][1] = ex2_pack(s[j0][2], s[j0][3]);
            ph[kk][2] = ex2_pack(s[j1][0], s[j1][1]);
            ph[kk][3] = ex2_pack(s[j1][2], s[j1][3]);
        }

        // O += ph * Vh
        const uint32_t vhb = sptr(CUR + 4608) + vrow;
        #pragma unroll
        for (int jv = 0; jv < 8; jv++) {
            uint32_t vh[8];
            LDSM4T(vh[0], vh[1], vh[2], vh[3], vhb + jv * 16);
            LDSM4T(vh[4], vh[5], vh[6], vh[7], vhb + jv * 16 + 32 * 144);
            #pragma unroll
            for (int kk = 0; kk < 4; kk++)
                MMA(o[jv], ph[kk], vh[kk * 2], vh[kk * 2 + 1]);
        }
        BARG(bar_id);
    }

    // join groups; Of overlaps the ring buffers
    __syncthreads();

    float* Of = (float*)sm;           // 64 x 66 fp32 = 16896 B
    const int gid = lane >> 2, tg = lane & 3;
    const int rA = r0 + gid;
    if (g == 1) {
        #pragma unroll
        for (int j = 0; j < 8; j++) {
            Of[rA * 66 + j * 8 + tg * 2]           = o[j][0];
            Of[rA * 66 + j * 8 + tg * 2 + 1]       = o[j][1];
            Of[(rA + 8) * 66 + j * 8 + tg * 2]     = o[j][2];
            Of[(rA + 8) * 66 + j * 8 + tg * 2 + 1] = o[j][3];
        }
    }
    __syncthreads();
    if (g == 0) {
        float* Op = g_Op + (size_t)kh * NTOK * OUTC;
        int row0 = q0 + rA, row1 = row0 + 8;
        #pragma unroll
        for (int j = 0; j < 8; j++) {
            float2 v0, v1;
            v0.x = o[j][0] + Of[rA * 66 + j * 8 + tg * 2];
            v0.y = o[j][1] + Of[rA * 66 + j * 8 + tg * 2 + 1];
            v1.x = o[j][2] + Of[(rA + 8) * 66 + j * 8 + tg * 2];
            v1.y = o[j][3] + Of[(rA + 8) * 66 + j * 8 + tg * 2 + 1];
            *(float2*)(Op + (size_t)row0 * 64 + j * 8 + tg * 2) = v0;
            *(float2*)(Op + (size_t)row1 * 64 + j * 8 + tg * 2) = v1;
        }
    }
}

// ---------------------------------------------------------------------------
// Combine: On = l2norm(Op[0] + Op[1]). One warp per token row.
// ---------------------------------------------------------------------------
__global__ void combine_kernel()
{
    int gtid = blockIdx.x * blockDim.x + threadIdx.x;
    int row  = gtid >> 5;
    int lane = gtid & 31;
    if (row >= NTOK) return;
    const float* p0 = g_Op + (size_t)row * 64;
    const float* p1 = g_Op + (size_t)(NTOK + row) * 64;
    float a0 = p0[lane]      + p1[lane];
    float a1 = p0[lane + 32] + p1[lane + 32];
    float ss = a0 * a0 + a1 * a1;
    #pragma unroll
    for (int d = 16; d >= 1; d >>= 1)
        ss += __shfl_xor_sync(0xffffffffu, ss, d);
    float inv = 1.0f / fmaxf(sqrtf(ss), 1e-12f);
    g_On[(size_t)row * 64 + lane]      = a0 * inv;
    g_On[(size_t)row * 64 + 32 + lane] = a1 * inv;
}

// ---------------------------------------------------------------------------
// Kernel C: sim split-K partials (transposed store) + warp-per-output reduce.
// ---------------------------------------------------------------------------
__global__ void sim_kernel()
{
    __shared__ float Va[64 * 68];
    __shared__ float Qa[64 * 68];
    const int aidx = blockIdx.x;
    const int tid  = threadIdx.x;

    #pragma unroll
    for (int i = 0; i < 16; i++) {
        int idx = tid + i * 256;
        int r = idx >> 6, t = idx & 63;
        size_t g = (size_t)(r * AA + aidx) * 64 + t;
        Va[r * 68 + t] = g_Vn[g];
        Qa[r * 68 + t] = g_On[g];
    }
    __syncthreads();

    const int ty = tid >> 4, tx = tid & 15;
    float acc[4][4] = {};
    for (int t = 0; t < 64; t += 4) {
        float4 vv[4], qv[4];
        #pragma unroll
        for (int ii = 0; ii < 4; ii++)
            vv[ii] = *(const float4*)(Va + (ty * 4 + ii) * 68 + t);
        #pragma unroll
        for (int jj = 0; jj < 4; jj++)
            qv[jj] = *(const float4*)(Qa + (tx * 4 + jj) * 68 + t);
        #pragma unroll
        for (int ii = 0; ii < 4; ii++)
            #pragma unroll
            for (int jj = 0; jj < 4; jj++) {
                acc[ii][jj] += vv[ii].x * qv[jj].x;
                acc[ii][jj] += vv[ii].y * qv[jj].y;
                acc[ii][jj] += vv[ii].z * qv[jj].z;
                acc[ii][jj] += vv[ii].w * qv[jj].w;
            }
    }

    #pragma unroll
    for (int ii = 0; ii < 4; ii++)
        #pragma unroll
        for (int jj = 0; jj < 4; jj++) {
            int ij = (ty * 4 + ii) * 64 + tx * 4 + jj;
            g_part[(size_t)ij * AA + aidx] = acc[ii][jj];
        }
}

__global__ void sim_reduce_kernel(float* __restrict__ out)
{
    int gw   = (blockIdx.x * blockDim.x + threadIdx.x) >> 5;
    int lane = threadIdx.x & 31;
    if (gw >= OUTC * OUTC) return;
    const float* p = g_part + (size_t)gw * AA;
    float s = p[lane] + p[lane + 32] + p[lane + 64] + p[lane + 96];
    #pragma unroll
    for (int d = 16; d >= 1; d >>= 1)
        s += __shfl_xor_sync(0xffffffffu, s, d);
    if (lane == 0) out[gw] = s * (1.0f / 128.0f);
}

// ---------------------------------------------------------------------------
extern "C" void kernel_launch(void* const* d_in, const int* in_sizes, int n_in,
                              void* d_out, int out_size)
{
    const float* feat = (const float*)d_in[0];
    const float* Wq   = (const float*)d_in[1];
    const float* bq   = (const float*)d_in[2];
    const float* Wk   = (const float*)d_in[3];
    const float* bk   = (const float*)d_in[4];
    const float* Wv   = (const float*)d_in[5];
    const float* bv   = (const float*)d_in[6];
    float* out = (float*)d_out;

    const int smemA = (2 * 64 * 132) * (int)sizeof(float);      // 67584
    const int smemB = (4608 + 4 * 9216) * (int)sizeof(__half);  // 82944
    cudaFuncSetAttribute(proj_kernel, cudaFuncAttributeMaxDynamicSharedMemorySize, smemA);
    cudaFuncSetAttribute(attn_kernel, cudaFuncAttributeMaxDynamicSharedMemorySize, smemB);

    proj_kernel<<<dim3(64, 3, 2), 256, smemA>>>(feat, Wq, bq, Wk, bk, Wv, bv);
    attn_kernel<<<256, 256, smemB>>>();
    combine_kernel<<<1024, 256>>>();
    sim_kernel<<<128, 256>>>();
    sim_reduce_kernel<<<512, 256>>>(out);
}

// round 10
// speedup vs baseline: 1.0761x; 1.0761x over previous
#include <cuda_runtime.h>
#include <cuda_fp16.h>
#include <cstdint>
#include <math.h>

#define BB   64
#define AA   128
#define INC  128
#define OUTC 64
#define NTOK 8192
#define LOG2E 1.4426950408889634f

// ---- scratch (device globals; no allocations allowed) ----------------------
// a-major layouts: index = (a*64 + b)*64 + d
__device__ float g_Vn[NTOK * OUTC];
__device__ float g_Op[2 * NTOK * OUTC];      // attention partial O per key-half
__device__ float g_part[OUTC * OUTC * AA];   // sim split-K partials [ij][a]
__device__ __align__(256) __half g_Qh[NTOK * OUTC];
__device__ __align__(256) __half g_Kh[NTOK * OUTC];
__device__ __align__(256) __half g_Vh[NTOK * OUTC];

// ---- helpers ----------------------------------------------------------------
__device__ __forceinline__ uint32_t sptr(const void* p) {
    return (uint32_t)__cvta_generic_to_shared(p);
}
__device__ __forceinline__ void cp16(void* smp, const void* gp) {
    asm volatile("cp.async.cg.shared.global [%0], [%1], 16;" :: "r"(sptr(smp)), "l"(gp));
}
#define CP_COMMIT()  asm volatile("cp.async.commit_group;")
#define CP_WAIT(n)   asm volatile("cp.async.wait_group %0;" :: "n"(n))
#define BARG(id)     asm volatile("bar.sync %0, 128;" :: "r"(id) : "memory")

// pack two fp32 into f16x2 and take exp2 elementwise
__device__ __forceinline__ uint32_t ex2_pack(float x, float y) {
    uint32_t d;
    asm("{\n\t"
        ".reg .b32 t;\n\t"
        "cvt.rn.f16x2.f32 t, %2, %1;\n\t"
        "ex2.approx.f16x2 %0, t;\n\t"
        "}" : "=r"(d) : "f"(x), "f"(y));
    return d;
}

#define LDSM4(d0,d1,d2,d3,a) \
  asm volatile("ldmatrix.sync.aligned.m8n8.x4.shared.b16 {%0,%1,%2,%3},[%4];" \
    : "=r"(d0),"=r"(d1),"=r"(d2),"=r"(d3) : "r"(a))
#define LDSM4T(d0,d1,d2,d3,a) \
  asm volatile("ldmatrix.sync.aligned.m8n8.x4.trans.shared.b16 {%0,%1,%2,%3},[%4];" \
    : "=r"(d0),"=r"(d1),"=r"(d2),"=r"(d3) : "r"(a))
#define MMA(d,a,b0,b1) \
  asm volatile("mma.sync.aligned.m16n8k16.row.col.f32.f16.f16.f32 " \
    "{%0,%1,%2,%3},{%4,%5,%6,%7},{%8,%9},{%0,%1,%2,%3};" \
    : "+f"(d[0]),"+f"(d[1]),"+f"(d[2]),"+f"(d[3]) \
    : "r"(a[0]),"r"(a[1]),"r"(a[2]),"r"(a[3]),"r"(b0),"r"(b1))

__device__ __forceinline__ uint32_t packh(float x, float y) {
    __half2 hh = __floats2half2_rn(x, y);
    return *reinterpret_cast<uint32_t*>(&hh);
}

// ---------------------------------------------------------------------------
// Kernel A: projections. grid (64 batches, 3 matrices, 2 a-halves), 256 thr.
// Q/K/V fp16 token-major (for attention). Vn fp32 a-major (for sim).
// ---------------------------------------------------------------------------
__global__ void proj_kernel(const float* __restrict__ feat,
                            const float* __restrict__ Wq, const float* __restrict__ bq,
                            const float* __restrict__ Wk, const float* __restrict__ bk,
                            const float* __restrict__ Wv, const float* __restrict__ bv)
{
    extern __shared__ float sA[];
    float* fs = sA;             // 64 x 132
    float* ws = sA + 64 * 132;  // 64 x 132

    const int b   = blockIdx.x;
    const int m   = blockIdx.y;
    const int a0  = blockIdx.z * 64;
    const int tid = threadIdx.x;
    const float* fb = feat + (size_t)b * INC * AA;

    const float* W    = (m == 0) ? Wq : (m == 1) ? Wk : Wv;
    const float* bias = (m == 0) ? bq : (m == 1) ? bk : bv;
    const float  scale = (m == 0) ? 0.125f * LOG2E : 1.0f;
    __half* Hh = (m == 0) ? g_Qh : (m == 1) ? g_Kh : g_Vh;

    #pragma unroll
    for (int i = 0; i < 32; i++) {
        int idx = tid + i * 256;
        int c = idx >> 6, a = idx & 63;
        fs[a * 132 + c] = fb[c * 128 + a0 + a];
    }
    #pragma unroll
    for (int i = 0; i < 32; i++) {
        int idx = tid + i * 256;
        int j = idx >> 7, c = idx & 127;
        ws[j * 132 + c] = W[idx];
    }
    __syncthreads();

    const int ty = tid >> 4;
    const int tx = tid & 15;

    float acc[4][4] = {};
    for (int c = 0; c < 128; c += 4) {
        float4 fv[4], wv[4];
        #pragma unroll
        for (int ii = 0; ii < 4; ii++)
            fv[ii] = *(const float4*)(fs + (ty * 4 + ii) * 132 + c);
        #pragma unroll
        for (int jj = 0; jj < 4; jj++)
            wv[jj] = *(const float4*)(ws + (tx * 4 + jj) * 132 + c);
        #pragma unroll
        for (int ii = 0; ii < 4; ii++)
            #pragma unroll
            for (int jj = 0; jj < 4; jj++) {
                acc[ii][jj] += fv[ii].x * wv[jj].x;
                acc[ii][jj] += fv[ii].y * wv[jj].y;
                acc[ii][jj] += fv[ii].z * wv[jj].z;
                acc[ii][jj] += fv[ii].w * wv[jj].w;
            }
    }

    float4 bv4 = *(const float4*)(bias + tx * 4);
    #pragma unroll
    for (int ii = 0; ii < 4; ii++) {
        int   a = a0 + ty * 4 + ii;
        size_t n = (size_t)b * AA + a;              // token-major (attention)
        float o0 = (acc[ii][0] + bv4.x) * scale;
        float o1 = (acc[ii][1] + bv4.y) * scale;
        float o2 = (acc[ii][2] + bv4.z) * scale;
        float o3 = (acc[ii][3] + bv4.w) * scale;
        *reinterpret_cast<uint32_t*>(Hh + n * OUTC + tx * 4)     = packh(o0, o1);
        *reinterpret_cast<uint32_t*>(Hh + n * OUTC + tx * 4 + 2) = packh(o2, o3);
        if (m == 2) {
            float ss = o0*o0 + o1*o1 + o2*o2 + o3*o3;
            ss += __shfl_xor_sync(0xffffffffu, ss, 1);
            ss += __shfl_xor_sync(0xffffffffu, ss, 2);
            ss += __shfl_xor_sync(0xffffffffu, ss, 4);
            ss += __shfl_xor_sync(0xffffffffu, ss, 8);
            float inv = 1.0f / fmaxf(sqrtf(ss), 1e-12f);
            float4 t;
            t.x = o0 * inv; t.y = o1 * inv; t.z = o2 * inv; t.w = o3 * inv;
            // a-major for sim: row = a*64 + b
            *(float4*)(g_Vn + ((size_t)a * BB + b) * OUTC + tx * 4) = t;
        }
    }
}

// ---------------------------------------------------------------------------
// Kernel B: attention on HMMA fp16, split-K over keys (2 CTAs/SM).
// Emits raw partial O to g_Op[half] in a-major layout; sim fuses the combine.
// ---------------------------------------------------------------------------
__global__ void __launch_bounds__(256, 2) attn_kernel()
{
    extern __shared__ __half sm[];
    const int tid  = threadIdx.x, lane = tid & 31, w = tid >> 5;
    const int g    = w >> 2;
    const int wl   = w & 3;
    const int gtid = tid & 127;
    const int q0   = (blockIdx.x >> 1) * 64;
    const int kh   = blockIdx.x & 1;
    const int kt0  = kh * 64;

    __half* QH = sm;            // 64 x 72 = 4608
    __half* ST = sm + 4608;     // 4 stages x 9216: [Kh,Vh] x 4608

    #pragma unroll
    for (int i = 0; i < 2; i++) {
        int idx = tid + i * 256, row = idx >> 3, c8 = idx & 7;
        cp16(QH + row * 72 + c8 * 8, g_Qh + (size_t)(q0 + row) * 64 + c8 * 8);
    }
    {
        __half* S0 = ST + (2 * g) * 9216;
        #pragma unroll
        for (int i = 0; i < 4; i++) {
            int idx = gtid + i * 128, row = idx >> 3, c8 = idx & 7;
            size_t gg = (size_t)((kt0 + g) * 64 + row) * 64 + c8 * 8;
            cp16(S0        + row * 72 + c8 * 8, g_Kh + gg);
            cp16(S0 + 4608 + row * 72 + c8 * 8, g_Vh + gg);
        }
    }
    CP_COMMIT();
    CP_WAIT(0);
    __syncthreads();

    uint32_t qh[4][4];
    const int r0 = wl * 16;
    {
        int row  = r0 + (lane & 15);
        int coff = (lane >> 4) * 8;
        #pragma unroll
        for (int kk = 0; kk < 4; kk++)
            LDSM4(qh[kk][0], qh[kk][1], qh[kk][2], qh[kk][3],
                  sptr(QH + row * 72 + kk * 16 + coff));
    }

    float o[8][4];
    #pragma unroll
    for (int j = 0; j < 8; j++) { o[j][0] = o[j][1] = o[j][2] = o[j][3] = 0.f; }

    const uint32_t krow = ((lane & 7) * 72 + (lane >> 3) * 8) * 2;
    const uint32_t vrow = lane * 144;
    const int bar_id = g + 1;

    for (int kt = kt0 + g; kt < kt0 + 64; kt += 2) {
        __half* CUR = ST + (2 * g + ((kt >> 1) & 1)) * 9216;
        if (kt + 2 < kt0 + 64) {
            __half* NXT = ST + (2 * g + (((kt + 2) >> 1) & 1)) * 9216;
            #pragma unroll
            for (int i = 0; i < 4; i++) {
                int idx = gtid + i * 128, row = idx >> 3, c8 = idx & 7;
                size_t gg = (size_t)((kt + 2) * 64 + row) * 64 + c8 * 8;
                cp16(NXT        + row * 72 + c8 * 8, g_Kh + gg);
                cp16(NXT + 4608 + row * 72 + c8 * 8, g_Vh + gg);
            }
            CP_COMMIT();
            CP_WAIT(1);
        } else {
            CP_WAIT(0);
        }
        BARG(bar_id);

        const uint32_t khb = sptr(CUR) + krow;

        float s[8][4];
        #pragma unroll
        for (int j = 0; j < 8; j++) {
            uint32_t bh[8];
            uint32_t off = j * (8 * 72 * 2);
            LDSM4(bh[0], bh[1], bh[2], bh[3], khb + off);
            LDSM4(bh[4], bh[5], bh[6], bh[7], khb + off + 64);
            s[j][0] = s[j][1] = s[j][2] = s[j][3] = 0.f;
            #pragma unroll
            for (int kk = 0; kk < 4; kk++)
                MMA(s[j], qh[kk], bh[kk * 2], bh[kk * 2 + 1]);
        }

        uint32_t ph[4][4];
        #pragma unroll
        for (int kk = 0; kk < 4; kk++) {
            int j0 = kk * 2, j1 = kk * 2 + 1;
            ph[kk][0] = ex2_pack(s[j0][0], s[j0][1]);
            ph[kk][1] = ex2_pack(s[j0][2], s[j0][3]);
            ph[kk][2] = ex2_pack(s[j1][0], s[j1][1]);
            ph[kk][3] = ex2_pack(s[j1][2], s[j1][3]);
        }

        const uint32_t vhb = sptr(CUR + 4608) + vrow;
        #pragma unroll
        for (int jv = 0; jv < 8; jv++) {
            uint32_t vh[8];
            LDSM4T(vh[0], vh[1], vh[2], vh[3], vhb + jv * 16);
            LDSM4T(vh[4], vh[5], vh[6], vh[7], vhb + jv * 16 + 32 * 144);
            #pragma unroll
            for (int kk = 0; kk < 4; kk++)
                MMA(o[jv], ph[kk], vh[kk * 2], vh[kk * 2 + 1]);
        }
        BARG(bar_id);
    }

    __syncthreads();

    float* Of = (float*)sm;           // 64 x 66 fp32 = 16896 B
    const int gid = lane >> 2, tg = lane & 3;
    const int rA = r0 + gid;
    if (g == 1) {
        #pragma unroll
        for (int j = 0; j < 8; j++) {
            Of[rA * 66 + j * 8 + tg * 2]           = o[j][0];
            Of[rA * 66 + j * 8 + tg * 2 + 1]       = o[j][1];
            Of[(rA + 8) * 66 + j * 8 + tg * 2]     = o[j][2];
            Of[(rA + 8) * 66 + j * 8 + tg * 2 + 1] = o[j][3];
        }
    }
    __syncthreads();
    if (g == 0) {
        float* Op = g_Op + (size_t)kh * NTOK * OUTC;
        // a-major: token = q0 + row -> a = token & 127, b = token >> 7
        int t0 = q0 + rA, t1 = t0 + 8;
        size_t m0 = ((size_t)(t0 & 127) * BB + (t0 >> 7)) * OUTC;
        size_t m1 = ((size_t)(t1 & 127) * BB + (t1 >> 7)) * OUTC;
        #pragma unroll
        for (int j = 0; j < 8; j++) {
            float2 v0, v1;
            v0.x = o[j][0] + Of[rA * 66 + j * 8 + tg * 2];
            v0.y = o[j][1] + Of[rA * 66 + j * 8 + tg * 2 + 1];
            v1.x = o[j][2] + Of[(rA + 8) * 66 + j * 8 + tg * 2];
            v1.y = o[j][3] + Of[(rA + 8) * 66 + j * 8 + tg * 2 + 1];
            *(float2*)(Op + m0 + j * 8 + tg * 2) = v0;
            *(float2*)(Op + m1 + j * 8 + tg * 2) = v1;
        }
    }
}

// ---------------------------------------------------------------------------
// Kernel C: fused combine + sim. One CTA per 'a'.
// Loads contiguous 16KB blocks (a-major), sums the two key-half partials,
// l2-normalizes rows in SMEM, then computes the 64x64 outer-product slice.
// ---------------------------------------------------------------------------
__global__ void sim_kernel()
{
    __shared__ float Va[64 * 68];
    __shared__ float Qa[64 * 68];
    const int aidx = blockIdx.x;
    const int tid  = threadIdx.x;
    const size_t base = (size_t)aidx * BB * OUTC;   // 4096 floats

    #pragma unroll
    for (int i = 0; i < 16; i++) {
        int idx = tid + i * 256;
        int r = idx >> 6, t = idx & 63;
        Va[r * 68 + t] = g_Vn[base + idx];
        Qa[r * 68 + t] = g_Op[base + idx] + g_Op[(size_t)NTOK * OUTC + base + idx];
    }
    __syncthreads();

    // l2-normalize Qa rows: 4 threads per row (row = tid>>2, part = tid&3)
    {
        int row = tid >> 2, part = tid & 3;
        float ss = 0.f;
        const float* q = Qa + row * 68 + part * 16;
        #pragma unroll
        for (int i = 0; i < 16; i++) ss += q[i] * q[i];
        ss += __shfl_xor_sync(0xffffffffu, ss, 1);
        ss += __shfl_xor_sync(0xffffffffu, ss, 2);
        float inv = 1.0f / fmaxf(sqrtf(ss), 1e-12f);
        float* qw = Qa + row * 68 + part * 16;
        #pragma unroll
        for (int i = 0; i < 16; i++) qw[i] *= inv;
    }
    __syncthreads();

    const int ty = tid >> 4, tx = tid & 15;
    float acc[4][4] = {};
    for (int t = 0; t < 64; t += 4) {
        float4 vv[4], qv[4];
        #pragma unroll
        for (int ii = 0; ii < 4; ii++)
            vv[ii] = *(const float4*)(Va + (ty * 4 + ii) * 68 + t);
        #pragma unroll
        for (int jj = 0; jj < 4; jj++)
            qv[jj] = *(const float4*)(Qa + (tx * 4 + jj) * 68 + t);
        #pragma unroll
        for (int ii = 0; ii < 4; ii++)
            #pragma unroll
            for (int jj = 0; jj < 4; jj++) {
                acc[ii][jj] += vv[ii].x * qv[jj].x;
                acc[ii][jj] += vv[ii].y * qv[jj].y;
                acc[ii][jj] += vv[ii].z * qv[jj].z;
                acc[ii][jj] += vv[ii].w * qv[jj].w;
            }
    }

    #pragma unroll
    for (int ii = 0; ii < 4; ii++)
        #pragma unroll
        for (int jj = 0; jj < 4; jj++) {
            int ij = (ty * 4 + ii) * 64 + tx * 4 + jj;
            g_part[(size_t)ij * AA + aidx] = acc[ii][jj];
        }
}

// warp-per-output reduce over contiguous 128 floats
__global__ void sim_reduce_kernel(float* __restrict__ out)
{
    int gw   = (blockIdx.x * blockDim.x + threadIdx.x) >> 5;
    int lane = threadIdx.x & 31;
    if (gw >= OUTC * OUTC) return;
    const float* p = g_part + (size_t)gw * AA;
    float s = p[lane] + p[lane + 32] + p[lane + 64] + p[lane + 96];
    #pragma unroll
    for (int d = 16; d >= 1; d >>= 1)
        s += __shfl_xor_sync(0xffffffffu, s, d);
    if (lane == 0) out[gw] = s * (1.0f / 128.0f);
}

// ---------------------------------------------------------------------------
extern "C" void kernel_launch(void* const* d_in, const int* in_sizes, int n_in,
                              void* d_out, int out_size)
{
    const float* feat = (const float*)d_in[0];
    const float* Wq   = (const float*)d_in[1];
    const float* bq   = (const float*)d_in[2];
    const float* Wk   = (const float*)d_in[3];
    const float* bk   = (const float*)d_in[4];
    const float* Wv   = (const float*)d_in[5];
    const float* bv   = (const float*)d_in[6];
    float* out = (float*)d_out;

    const int smemA = (2 * 64 * 132) * (int)sizeof(float);      // 67584
    const int smemB = (4608 + 4 * 9216) * (int)sizeof(__half);  // 82944
    cudaFuncSetAttribute(proj_kernel, cudaFuncAttributeMaxDynamicSharedMemorySize, smemA);
    cudaFuncSetAttribute(attn_kernel, cudaFuncAttributeMaxDynamicSharedMemorySize, smemB);

    proj_kernel<<<dim3(64, 3, 2), 256, smemA>>>(feat, Wq, bq, Wk, bk, Wv, bv);
    attn_kernel<<<256, 256, smemB>>>();
    sim_kernel<<<128, 256>>>();
    sim_reduce_kernel<<<512, 256>>>(out);
}

// round 11
// speedup vs baseline: 1.3913x; 1.2929x over previous
#include <cuda_runtime.h>
#include <cuda_fp16.h>
#include <cstdint>
#include <math.h>

#define BB   64
#define AA   128
#define INC  128
#define OUTC 64
#define NTOK 8192
#define LOG2E 1.4426950408889634f

// ---- scratch (device globals; no allocations allowed) ----------------------
__device__ __align__(16) float g_Vn[NTOK * OUTC];          // a-major
__device__ __align__(16) float g_Op[2 * NTOK * OUTC];      // a-major partial O
__device__ __align__(16) float g_part[OUTC * OUTC * AA];   // [ij][a]
__device__ __align__(256) __half g_Qh[NTOK * OUTC];
__device__ __align__(256) __half g_Kh[NTOK * OUTC];
__device__ __align__(256) __half g_Vh[NTOK * OUTC];

// ---- helpers ----------------------------------------------------------------
__device__ __forceinline__ uint32_t sptr(const void* p) {
    return (uint32_t)__cvta_generic_to_shared(p);
}
__device__ __forceinline__ void cp16(void* smp, const void* gp) {
    asm volatile("cp.async.cg.shared.global [%0], [%1], 16;" :: "r"(sptr(smp)), "l"(gp));
}
#define CP_COMMIT()  asm volatile("cp.async.commit_group;")
#define CP_WAIT(n)   asm volatile("cp.async.wait_group %0;" :: "n"(n))
#define BARG(id)     asm volatile("bar.sync %0, 128;" :: "r"(id) : "memory")

__device__ __forceinline__ uint32_t ex2_pack(float x, float y) {
    uint32_t d;
    asm("{\n\t"
        ".reg .b32 t;\n\t"
        "cvt.rn.f16x2.f32 t, %2, %1;\n\t"
        "ex2.approx.f16x2 %0, t;\n\t"
        "}" : "=r"(d) : "f"(x), "f"(y));
    return d;
}

#define LDSM4(d0,d1,d2,d3,a) \
  asm volatile("ldmatrix.sync.aligned.m8n8.x4.shared.b16 {%0,%1,%2,%3},[%4];" \
    : "=r"(d0),"=r"(d1),"=r"(d2),"=r"(d3) : "r"(a))
#define LDSM4T(d0,d1,d2,d3,a) \
  asm volatile("ldmatrix.sync.aligned.m8n8.x4.trans.shared.b16 {%0,%1,%2,%3},[%4];" \
    : "=r"(d0),"=r"(d1),"=r"(d2),"=r"(d3) : "r"(a))
#define MMA(d,a,b0,b1) \
  asm volatile("mma.sync.aligned.m16n8k16.row.col.f32.f16.f16.f32 " \
    "{%0,%1,%2,%3},{%4,%5,%6,%7},{%8,%9},{%0,%1,%2,%3};" \
    : "+f"(d[0]),"+f"(d[1]),"+f"(d[2]),"+f"(d[3]) \
    : "r"(a[0]),"r"(a[1]),"r"(a[2]),"r"(a[3]),"r"(b0),"r"(b1))

__device__ __forceinline__ uint32_t packh(float x, float y) {
    __half2 hh = __floats2half2_rn(x, y);
    return *reinterpret_cast<uint32_t*>(&hh);
}

// ---------------------------------------------------------------------------
// Kernel A: projections on HMMA. grid (64 batches, 3 matrices), 256 threads.
// fs = features^T [128a x 128c] fp16 (pitch 136), ws = W [64j x 128c] fp16.
// Each warp owns 16 a-rows; 8 n-tiles x 8 k-steps of m16n8k16.
// Q/K/V fp16 token-major; Vn fp32 a-major with fused l2norm (m==2).
// ---------------------------------------------------------------------------
__global__ void __launch_bounds__(256) proj_kernel(
                            const float* __restrict__ feat,
                            const float* __restrict__ Wq, const float* __restrict__ bq,
                            const float* __restrict__ Wk, const float* __restrict__ bk,
                            const float* __restrict__ Wv, const float* __restrict__ bv)
{
    extern __shared__ __half sP[];
    __half* fs = sP;              // 128 x 136
    __half* ws = sP + 128 * 136;  // 64 x 136

    const int b   = blockIdx.x;
    const int m   = blockIdx.y;
    const int tid = threadIdx.x, lane = tid & 31, w = tid >> 5;
    const float* fb = feat + (size_t)b * INC * AA;

    const float* W    = (m == 0) ? Wq : (m == 1) ? Wk : Wv;
    const float* bias = (m == 0) ? bq : (m == 1) ? bk : bv;
    const float  scale = (m == 0) ? 0.125f * LOG2E : 1.0f;
    __half* Hh = (m == 0) ? g_Qh : (m == 1) ? g_Kh : g_Vh;

    // stage A transposed: fs[a][c] = feat[b][c][a] (coalesced LDG along a)
    #pragma unroll 8
    for (int i = 0; i < 64; i++) {
        int idx = tid + i * 256;
        int c = idx >> 7, a = idx & 127;
        fs[a * 136 + c] = __float2half(fb[c * 128 + a]);
    }
    // stage B: ws[j][c] = W[j][c]
    #pragma unroll 8
    for (int i = 0; i < 32; i++) {
        int idx = tid + i * 256;
        int j = idx >> 7, c = idx & 127;
        ws[j * 136 + c] = __float2half(W[idx]);
    }
    __syncthreads();

    // A fragments: rows r0..r0+15, 8 k-steps
    uint32_t af[8][4];
    const int r0 = w * 16;
    {
        int row  = r0 + (lane & 15);
        int coff = (lane >> 4) * 8;
        #pragma unroll
        for (int kk = 0; kk < 8; kk++)
            LDSM4(af[kk][0], af[kk][1], af[kk][2], af[kk][3],
                  sptr(fs + row * 136 + kk * 16 + coff));
    }

    const uint32_t kb = sptr(ws) + ((lane & 7) * 136 + (lane >> 3) * 8) * 2;

    float s[8][4];
    #pragma unroll
    for (int j = 0; j < 8; j++) {
        uint32_t bh[16];
        uint32_t off = j * (8 * 136 * 2);
        LDSM4(bh[0],  bh[1],  bh[2],  bh[3],  kb + off);
        LDSM4(bh[4],  bh[5],  bh[6],  bh[7],  kb + off + 64);
        LDSM4(bh[8],  bh[9],  bh[10], bh[11], kb + off + 128);
        LDSM4(bh[12], bh[13], bh[14], bh[15], kb + off + 192);
        s[j][0] = s[j][1] = s[j][2] = s[j][3] = 0.f;
        #pragma unroll
        for (int kk = 0; kk < 8; kk++)
            MMA(s[j], af[kk], bh[kk * 2], bh[kk * 2 + 1]);
    }

    // epilogue: bias + scale, pack fp16 token-major; fused Vn (m==2)
    const int gid = lane >> 2, tg = lane & 3;
    const int a0r = r0 + gid, a1r = a0r + 8;
    const size_t n0 = (size_t)b * AA + a0r;
    const size_t n1 = (size_t)b * AA + a1r;
    float ss0 = 0.f, ss1 = 0.f;
    #pragma unroll
    for (int j = 0; j < 8; j++) {
        int col = j * 8 + tg * 2;
        float bx = bias[col], by = bias[col + 1];
        float o0 = (s[j][0] + bx) * scale;
        float o1 = (s[j][1] + by) * scale;
        float o2 = (s[j][2] + bx) * scale;
        float o3 = (s[j][3] + by) * scale;
        s[j][0] = o0; s[j][1] = o1; s[j][2] = o2; s[j][3] = o3;
        *reinterpret_cast<uint32_t*>(Hh + n0 * OUTC + col) = packh(o0, o1);
        *reinterpret_cast<uint32_t*>(Hh + n1 * OUTC + col) = packh(o2, o3);
        ss0 += o0 * o0 + o1 * o1;
        ss1 += o2 * o2 + o3 * o3;
    }
    if (m == 2) {
        ss0 += __shfl_xor_sync(0xffffffffu, ss0, 1);
        ss0 += __shfl_xor_sync(0xffffffffu, ss0, 2);
        ss1 += __shfl_xor_sync(0xffffffffu, ss1, 1);
        ss1 += __shfl_xor_sync(0xffffffffu, ss1, 2);
        float i0 = 1.f / fmaxf(sqrtf(ss0), 1e-12f);
        float i1 = 1.f / fmaxf(sqrtf(ss1), 1e-12f);
        size_t m0 = ((size_t)a0r * BB + b) * OUTC;
        size_t m1 = ((size_t)a1r * BB + b) * OUTC;
        #pragma unroll
        for (int j = 0; j < 8; j++) {
            int col = j * 8 + tg * 2;
            float2 v0; v0.x = s[j][0] * i0; v0.y = s[j][1] * i0;
            float2 v1; v1.x = s[j][2] * i1; v1.y = s[j][3] * i1;
            *(float2*)(g_Vn + m0 + col) = v0;
            *(float2*)(g_Vn + m1 + col) = v1;
        }
    }
}

// ---------------------------------------------------------------------------
// Kernel B: attention on HMMA fp16, split-K over keys (2 CTAs/SM).
// Emits raw partial O to g_Op[half] in a-major layout; sim fuses the combine.
// ---------------------------------------------------------------------------
__global__ void __launch_bounds__(256, 2) attn_kernel()
{
    extern __shared__ __half sm[];
    const int tid  = threadIdx.x, lane = tid & 31, w = tid >> 5;
    const int g    = w >> 2;
    const int wl   = w & 3;
    const int gtid = tid & 127;
    const int q0   = (blockIdx.x >> 1) * 64;
    const int kh   = blockIdx.x & 1;
    const int kt0  = kh * 64;

    __half* QH = sm;            // 64 x 72 = 4608
    __half* ST = sm + 4608;     // 4 stages x 9216: [Kh,Vh] x 4608

    #pragma unroll
    for (int i = 0; i < 2; i++) {
        int idx = tid + i * 256, row = idx >> 3, c8 = idx & 7;
        cp16(QH + row * 72 + c8 * 8, g_Qh + (size_t)(q0 + row) * 64 + c8 * 8);
    }
    {
        __half* S0 = ST + (2 * g) * 9216;
        #pragma unroll
        for (int i = 0; i < 4; i++) {
            int idx = gtid + i * 128, row = idx >> 3, c8 = idx & 7;
            size_t gg = (size_t)((kt0 + g) * 64 + row) * 64 + c8 * 8;
            cp16(S0        + row * 72 + c8 * 8, g_Kh + gg);
            cp16(S0 + 4608 + row * 72 + c8 * 8, g_Vh + gg);
        }
    }
    CP_COMMIT();
    CP_WAIT(0);
    __syncthreads();

    uint32_t qh[4][4];
    const int r0 = wl * 16;
    {
        int row  = r0 + (lane & 15);
        int coff = (lane >> 4) * 8;
        #pragma unroll
        for (int kk = 0; kk < 4; kk++)
            LDSM4(qh[kk][0], qh[kk][1], qh[kk][2], qh[kk][3],
                  sptr(QH + row * 72 + kk * 16 + coff));
    }

    float o[8][4];
    #pragma unroll
    for (int j = 0; j < 8; j++) { o[j][0] = o[j][1] = o[j][2] = o[j][3] = 0.f; }

    const uint32_t krow = ((lane & 7) * 72 + (lane >> 3) * 8) * 2;
    const uint32_t vrow = lane * 144;
    const int bar_id = g + 1;

    for (int kt = kt0 + g; kt < kt0 + 64; kt += 2) {
        __half* CUR = ST + (2 * g + ((kt >> 1) & 1)) * 9216;
        if (kt + 2 < kt0 + 64) {
            __half* NXT = ST + (2 * g + (((kt + 2) >> 1) & 1)) * 9216;
            #pragma unroll
            for (int i = 0; i < 4; i++) {
                int idx = gtid + i * 128, row = idx >> 3, c8 = idx & 7;
                size_t gg = (size_t)((kt + 2) * 64 + row) * 64 + c8 * 8;
                cp16(NXT        + row * 72 + c8 * 8, g_Kh + gg);
                cp16(NXT + 4608 + row * 72 + c8 * 8, g_Vh + gg);
            }
            CP_COMMIT();
            CP_WAIT(1);
        } else {
            CP_WAIT(0);
        }
        BARG(bar_id);

        const uint32_t khb = sptr(CUR) + krow;

        float s[8][4];
        #pragma unroll
        for (int j = 0; j < 8; j++) {
            uint32_t bh[8];
            uint32_t off = j * (8 * 72 * 2);
            LDSM4(bh[0], bh[1], bh[2], bh[3], khb + off);
            LDSM4(bh[4], bh[5], bh[6], bh[7], khb + off + 64);
            s[j][0] = s[j][1] = s[j][2] = s[j][3] = 0.f;
            #pragma unroll
            for (int kk = 0; kk < 4; kk++)
                MMA(s[j], qh[kk], bh[kk * 2], bh[kk * 2 + 1]);
        }

        uint32_t ph[4][4];
        #pragma unroll
        for (int kk = 0; kk < 4; kk++) {
            int j0 = kk * 2, j1 = kk * 2 + 1;
            ph[kk][0] = ex2_pack(s[j0][0], s[j0][1]);
            ph[kk][1] = ex2_pack(s[j0][2], s[j0][3]);
            ph[kk][2] = ex2_pack(s[j1][0], s[j1][1]);
            ph[kk][3] = ex2_pack(s[j1][2], s[j1][3]);
        }

        const uint32_t vhb = sptr(CUR + 4608) + vrow;
        #pragma unroll
        for (int jv = 0; jv < 8; jv++) {
            uint32_t vh[8];
            LDSM4T(vh[0], vh[1], vh[2], vh[3], vhb + jv * 16);
            LDSM4T(vh[4], vh[5], vh[6], vh[7], vhb + jv * 16 + 32 * 144);
            #pragma unroll
            for (int kk = 0; kk < 4; kk++)
                MMA(o[jv], ph[kk], vh[kk * 2], vh[kk * 2 + 1]);
        }
        BARG(bar_id);
    }

    __syncthreads();

    float* Of = (float*)sm;           // 64 x 66 fp32 = 16896 B
    const int gid = lane >> 2, tg = lane & 3;
    const int rA = r0 + gid;
    if (g == 1) {
        #pragma unroll
        for (int j = 0; j < 8; j++) {
            Of[rA * 66 + j * 8 + tg * 2]           = o[j][0];
            Of[rA * 66 + j * 8 + tg * 2 + 1]       = o[j][1];
            Of[(rA + 8) * 66 + j * 8 + tg * 2]     = o[j][2];
            Of[(rA + 8) * 66 + j * 8 + tg * 2 + 1] = o[j][3];
        }
    }
    __syncthreads();
    if (g == 0) {
        float* Op = g_Op + (size_t)kh * NTOK * OUTC;
        int t0 = q0 + rA, t1 = t0 + 8;
        size_t m0 = ((size_t)(t0 & 127) * BB + (t0 >> 7)) * OUTC;
        size_t m1 = ((size_t)(t1 & 127) * BB + (t1 >> 7)) * OUTC;
        #pragma unroll
        for (int j = 0; j < 8; j++) {
            float2 v0, v1;
            v0.x = o[j][0] + Of[rA * 66 + j * 8 + tg * 2];
            v0.y = o[j][1] + Of[rA * 66 + j * 8 + tg * 2 + 1];
            v1.x = o[j][2] + Of[(rA + 8) * 66 + j * 8 + tg * 2];
            v1.y = o[j][3] + Of[(rA + 8) * 66 + j * 8 + tg * 2 + 1];
            *(float2*)(Op + m0 + j * 8 + tg * 2) = v0;
            *(float2*)(Op + m1 + j * 8 + tg * 2) = v1;
        }
    }
}

// ---------------------------------------------------------------------------
// Kernel C: fused combine + sim. One CTA per 'a'. Contiguous 16KB loads.
// ---------------------------------------------------------------------------
__global__ void sim_kernel()
{
    __shared__ float Va[64 * 68];
    __shared__ float Qa[64 * 68];
    const int aidx = blockIdx.x;
    const int tid  = threadIdx.x;
    const size_t base = (size_t)aidx * BB * OUTC;

    #pragma unroll
    for (int i = 0; i < 16; i++) {
        int idx = tid + i * 256;
        int r = idx >> 6, t = idx & 63;
        Va[r * 68 + t] = g_Vn[base + idx];
        Qa[r * 68 + t] = g_Op[base + idx] + g_Op[(size_t)NTOK * OUTC + base + idx];
    }
    __syncthreads();

    {
        int row = tid >> 2, part = tid & 3;
        float ss = 0.f;
        const float* q = Qa + row * 68 + part * 16;
        #pragma unroll
        for (int i = 0; i < 16; i++) ss += q[i] * q[i];
        ss += __shfl_xor_sync(0xffffffffu, ss, 1);
        ss += __shfl_xor_sync(0xffffffffu, ss, 2);
        float inv = 1.0f / fmaxf(sqrtf(ss), 1e-12f);
        float* qw = Qa + row * 68 + part * 16;
        #pragma unroll
        for (int i = 0; i < 16; i++) qw[i] *= inv;
    }
    __syncthreads();

    const int ty = tid >> 4, tx = tid & 15;
    float acc[4][4] = {};
    for (int t = 0; t < 64; t += 4) {
        float4 vv[4], qv[4];
        #pragma unroll
        for (int ii = 0; ii < 4; ii++)
            vv[ii] = *(const float4*)(Va + (ty * 4 + ii) * 68 + t);
        #pragma unroll
        for (int jj = 0; jj < 4; jj++)
            qv[jj] = *(const float4*)(Qa + (tx * 4 + jj) * 68 + t);
        #pragma unroll
        for (int ii = 0; ii < 4; ii++)
            #pragma unroll
            for (int jj = 0; jj < 4; jj++) {
                acc[ii][jj] += vv[ii].x * qv[jj].x;
                acc[ii][jj] += vv[ii].y * qv[jj].y;
                acc[ii][jj] += vv[ii].z * qv[jj].z;
                acc[ii][jj] += vv[ii].w * qv[jj].w;
            }
    }

    #pragma unroll
    for (int ii = 0; ii < 4; ii++)
        #pragma unroll
        for (int jj = 0; jj < 4; jj++) {
            int ij = (ty * 4 + ii) * 64 + tx * 4 + jj;
            g_part[(size_t)ij * AA + aidx] = acc[ii][jj];
        }
}

// warp-per-output reduce, one float4 per lane (512B coalesced per warp)
__global__ void sim_reduce_kernel(float* __restrict__ out)
{
    int gw   = (blockIdx.x * blockDim.x + threadIdx.x) >> 5;
    int lane = threadIdx.x & 31;
    if (gw >= OUTC * OUTC) return;
    float4 v = *((const float4*)(g_part + (size_t)gw * AA) + lane);
    float s = (v.x + v.y) + (v.z + v.w);
    #pragma unroll
    for (int d = 16; d >= 1; d >>= 1)
        s += __shfl_xor_sync(0xffffffffu, s, d);
    if (lane == 0) out[gw] = s * (1.0f / 128.0f);
}

// ---------------------------------------------------------------------------
extern "C" void kernel_launch(void* const* d_in, const int* in_sizes, int n_in,
                              void* d_out, int out_size)
{
    const float* feat = (const float*)d_in[0];
    const float* Wq   = (const float*)d_in[1];
    const float* bq   = (const float*)d_in[2];
    const float* Wk   = (const float*)d_in[3];
    const float* bk   = (const float*)d_in[4];
    const float* Wv   = (const float*)d_in[5];
    const float* bv   = (const float*)d_in[6];
    float* out = (float*)d_out;

    const int smemA = (128 * 136 + 64 * 136) * (int)sizeof(__half);  // 52224
    const int smemB = (4608 + 4 * 9216) * (int)sizeof(__half);       // 82944
    cudaFuncSetAttribute(proj_kernel, cudaFuncAttributeMaxDynamicSharedMemorySize, smemA);
    cudaFuncSetAttribute(attn_kernel, cudaFuncAttributeMaxDynamicSharedMemorySize, smemB);

    proj_kernel<<<dim3(64, 3), 256, smemA>>>(feat, Wq, bq, Wk, bk, Wv, bv);
    attn_kernel<<<256, 256, smemB>>>();
    sim_kernel<<<128, 256>>>();
    sim_reduce_kernel<<<512, 256>>>(out);
}